// round 5
// baseline (speedup 1.0000x reference)
#include <cuda_runtime.h>
#include <cuda_bf16.h>
#include <math.h>
#include <stdint.h>

#define LL 2
#define NN1 8
#define NN2 8
#define PP 1024
#define DD 768
#define PH 32
#define PW 32
#define IMG 512

// Scratch (device globals; no allocation allowed)
__device__ char  g_qa[LL * NN1 * PP * DD];   // int8 quantized normalized feats
__device__ char  g_qb[LL * NN2 * PP * DD];   // int8 quantized normalized nfeats
__device__ float g_sa[LL * NN1 * PP];        // per-row dequant scale (A)
__device__ float g_sb[LL * NN2 * PP];        // per-row dequant scale (B)
__device__ float g_maxdot[LL * NN1 * NN2 * PP]; // max_p2 cos-sim
__device__ float g_sp[LL * NN1 * NN2 * PP];
__device__ float g_maxp[LL * NN1 * NN2];
__device__ float g_spbar[NN1 * PP];

// ---------------------------------------------------------------------------
// Kernel 1: L2-normalize rows of [rows,768], quantize to int8 w/ per-row scale.
// One warp per row.
// ---------------------------------------------------------------------------
__global__ __launch_bounds__(256) void normq_kernel(const float* __restrict__ in,
                                                    int which, int nrows) {
    int row  = blockIdx.x * 8 + (threadIdx.x >> 5);
    int lane = threadIdx.x & 31;
    if (row >= nrows) return;

    const float4* src = (const float4*)(in + (size_t)row * DD);
    float4 v[6];
    float ss = 0.f;
#pragma unroll
    for (int i = 0; i < 6; i++) {
        v[i] = src[lane + 32 * i];
        ss += v[i].x * v[i].x + v[i].y * v[i].y + v[i].z * v[i].z + v[i].w * v[i].w;
    }
#pragma unroll
    for (int o = 16; o > 0; o >>= 1) ss += __shfl_xor_sync(0xffffffffu, ss, o);
    float inv = 1.0f / sqrtf(ss);

    float w[24];
    float amax = 0.f;
#pragma unroll
    for (int i = 0; i < 6; i++) {
        w[4 * i + 0] = v[i].x * inv; w[4 * i + 1] = v[i].y * inv;
        w[4 * i + 2] = v[i].z * inv; w[4 * i + 3] = v[i].w * inv;
#pragma unroll
        for (int j = 0; j < 4; j++) amax = fmaxf(amax, fabsf(w[4 * i + j]));
    }
#pragma unroll
    for (int o = 16; o > 0; o >>= 1)
        amax = fmaxf(amax, __shfl_xor_sync(0xffffffffu, amax, o));

    float qs = 127.0f / amax;
    char4* dst = (char4*)((which ? g_qb : g_qa) + (size_t)row * DD);
#pragma unroll
    for (int i = 0; i < 6; i++) {
        char4 c;
        c.x = (char)__float2int_rn(w[4 * i + 0] * qs);
        c.y = (char)__float2int_rn(w[4 * i + 1] * qs);
        c.z = (char)__float2int_rn(w[4 * i + 2] * qs);
        c.w = (char)__float2int_rn(w[4 * i + 3] * qs);
        dst[lane + 32 * i] = c;
    }
    if (lane == 0) (which ? g_sb : g_sa)[row] = amax * (1.0f / 127.0f);
}

// ---------------------------------------------------------------------------
// Kernel 2: fused int8 IMMA GEMM + scaled row-max.
// Pair = (l,n1,n2): S = sca*scb*(Qa[1024,768]*Qb[1024,768]^T); row max over cols.
// Block: 128-row strip of A; 8 column tiles of 128; 256 thr = 8 warps (2m x 4n),
// warp tile 64x32, mma.m16n8k32.s8; BK=64 bytes, cp.async double-buffered,
// smem rows padded to 80 bytes (conflict-free ldmatrix).
// ---------------------------------------------------------------------------
#define BM 128
#define BN 128
#define BK 64
#define RS 80     // smem row stride in bytes (64 + 16 pad)

#define CP16(dst_u32, src_ptr) \
    asm volatile("cp.async.cg.shared.global [%0], [%1], 16;\n" :: "r"(dst_u32), "l"(src_ptr))

__device__ __forceinline__ void ldsm4(uint32_t* r, uint32_t addr) {
    asm volatile("ldmatrix.sync.aligned.m8n8.x4.shared.b16 {%0,%1,%2,%3}, [%4];"
                 : "=r"(r[0]), "=r"(r[1]), "=r"(r[2]), "=r"(r[3]) : "r"(addr));
}

__global__ __launch_bounds__(256, 1) void distmax_i8() {
    __shared__ __align__(16) char sA[2][BM * RS];
    __shared__ __align__(16) char sB[2][BN * RS];
    __shared__ float part[4 * 128];

    const int pair = blockIdx.y;          // ((l*8 + n1)*8 + n2)
    const int l  = pair >> 6;
    const int n1 = (pair >> 3) & 7;
    const int n2 = pair & 7;
    const char* __restrict__ A =
        g_qa + (((size_t)(l * NN1 + n1)) * PP + blockIdx.x * BM) * DD;
    const char* __restrict__ B = g_qb + ((size_t)(l * NN2 + n2)) * PP * DD;
    const float* __restrict__ sbRow = g_sb + (size_t)(l * NN2 + n2) * PP;

    const int tid  = threadIdx.x;
    const int lane = tid & 31;
    const int warp = tid >> 5;
    const int wm = warp >> 2;        // 0..1
    const int wn = warp & 3;         // 0..3
    const int g  = lane >> 2;        // 0..7
    const int t4 = lane & 3;         // 0..3
    const int sub = lane >> 3;       // 0..3 (ldmatrix sub-matrix)
    const int lr8 = lane & 7;

    // cp.async mapping: thread -> (row ldr, 16B chunk ldc) and (+64 rows)
    const int ldr = tid >> 2;        // 0..63
    const int ldc = tid & 3;

    uint32_t sA0 = (uint32_t)__cvta_generic_to_shared(&sA[0][0]);
    uint32_t sB0 = (uint32_t)__cvta_generic_to_shared(&sB[0][0]);
    const uint32_t dOff0 = (uint32_t)(ldr * RS + ldc * 16);
    const uint32_t dOff1 = (uint32_t)((ldr + 64) * RS + ldc * 16);

    const char* aSrc0 = A + (size_t)ldr * DD + ldc * 16;
    const char* aSrc1 = aSrc0 + (size_t)64 * DD;

    // ldmatrix per-lane byte offsets (b16 view of 8x16B submatrices)
    const uint32_t aLds = (uint32_t)((wm * 64 + (sub & 1) * 8 + lr8) * RS +
                                     (sub >> 1) * 16);
    const uint32_t bLds = (uint32_t)((wn * 32 + (sub & 1) * 8 + lr8) * RS +
                                     (sub >> 1) * 16);

    float rmax[4][2];
#pragma unroll
    for (int i = 0; i < 4; i++) { rmax[i][0] = -1e30f; rmax[i][1] = -1e30f; }

    for (int ct = 0; ct < PP / BN; ct++) {
        const char* bSrc0 = B + (size_t)(ct * BN + ldr) * DD + ldc * 16;
        const char* bSrc1 = bSrc0 + (size_t)64 * DD;

        // per-thread column scales for this tile (col = wn*32 + ni*8 + 2*t4 + r)
        float sbv[4][2];
#pragma unroll
        for (int ni = 0; ni < 4; ni++) {
            int c = ct * BN + wn * 32 + ni * 8 + 2 * t4;
            sbv[ni][0] = __ldg(sbRow + c);
            sbv[ni][1] = __ldg(sbRow + c + 1);
        }

        int acc[4][4][4];
#pragma unroll
        for (int mi = 0; mi < 4; mi++)
#pragma unroll
            for (int ni = 0; ni < 4; ni++)
#pragma unroll
                for (int r = 0; r < 4; r++) acc[mi][ni][r] = 0;

        // prime: stage 0 -> buffer 0
        CP16(sA0 + dOff0, aSrc0);
        CP16(sA0 + dOff1, aSrc1);
        CP16(sB0 + dOff0, bSrc0);
        CP16(sB0 + dOff1, bSrc1);
        asm volatile("cp.async.commit_group;\n");

        for (int ks = 0; ks < DD / BK; ks++) {
            const int cur = ks & 1;
            if (ks < DD / BK - 1) {
                const int k0 = (ks + 1) * BK;
                uint32_t bufo = (uint32_t)((cur ^ 1) * BM * RS);
                CP16(sA0 + bufo + dOff0, aSrc0 + k0);
                CP16(sA0 + bufo + dOff1, aSrc1 + k0);
                CP16(sB0 + bufo + dOff0, bSrc0 + k0);
                CP16(sB0 + bufo + dOff1, bSrc1 + k0);
                asm volatile("cp.async.commit_group;\n");
                asm volatile("cp.async.wait_group 1;\n");
            } else {
                asm volatile("cp.async.wait_group 0;\n");
            }
            __syncthreads();

            const uint32_t aBuf = sA0 + (uint32_t)(cur * BM * RS);
            const uint32_t bBuf = sB0 + (uint32_t)(cur * BN * RS);

#pragma unroll
            for (int k32 = 0; k32 < 2; k32++) {
                uint32_t a[4][4], b[2][4];
#pragma unroll
                for (int mi = 0; mi < 4; mi++)
                    ldsm4(a[mi], aBuf + aLds + (uint32_t)(mi * 16 * RS + k32 * 32));
#pragma unroll
                for (int np = 0; np < 2; np++)
                    ldsm4(b[np], bBuf + bLds + (uint32_t)(np * 16 * RS + k32 * 32));
#pragma unroll
                for (int mi = 0; mi < 4; mi++)
#pragma unroll
                    for (int ni = 0; ni < 4; ni++) {
                        asm volatile(
                            "mma.sync.aligned.m16n8k32.row.col.s32.s8.s8.s32 "
                            "{%0,%1,%2,%3},{%4,%5,%6,%7},{%8,%9},{%0,%1,%2,%3};\n"
                            : "+r"(acc[mi][ni][0]), "+r"(acc[mi][ni][1]),
                              "+r"(acc[mi][ni][2]), "+r"(acc[mi][ni][3])
                            : "r"(a[mi][0]), "r"(a[mi][1]), "r"(a[mi][2]), "r"(a[mi][3]),
                              "r"(b[ni >> 1][ni & 1]), "r"(b[ni >> 1][(ni & 1) + 2]));
                    }
            }
            __syncthreads();
        }

        // fold this column tile into running row max (apply column scale)
        // c0,c1 -> row g cols +0,+1; c2,c3 -> row g+8 same cols
#pragma unroll
        for (int mi = 0; mi < 4; mi++) {
            float m0 = -1e30f, m1 = -1e30f;
#pragma unroll
            for (int ni = 0; ni < 4; ni++) {
                m0 = fmaxf(m0, fmaxf((float)acc[mi][ni][0] * sbv[ni][0],
                                     (float)acc[mi][ni][1] * sbv[ni][1]));
                m1 = fmaxf(m1, fmaxf((float)acc[mi][ni][2] * sbv[ni][0],
                                     (float)acc[mi][ni][3] * sbv[ni][1]));
            }
            rmax[mi][0] = fmaxf(rmax[mi][0], m0);
            rmax[mi][1] = fmaxf(rmax[mi][1], m1);
        }
    }

    // reduce across the 4 lanes sharing g (t4 = lane&3)
#pragma unroll
    for (int o = 1; o <= 2; o <<= 1) {
#pragma unroll
        for (int mi = 0; mi < 4; mi++) {
            rmax[mi][0] = fmaxf(rmax[mi][0], __shfl_xor_sync(0xffffffffu, rmax[mi][0], o));
            rmax[mi][1] = fmaxf(rmax[mi][1], __shfl_xor_sync(0xffffffffu, rmax[mi][1], o));
        }
    }
    if (t4 == 0) {
#pragma unroll
        for (int mi = 0; mi < 4; mi++) {
            int r = wm * 64 + mi * 16 + g;
            part[wn * 128 + r] = rmax[mi][0];
            part[wn * 128 + r + 8] = rmax[mi][1];
        }
    }
    __syncthreads();
    if (tid < 128) {
        float v = fmaxf(fmaxf(part[tid], part[128 + tid]),
                        fmaxf(part[256 + tid], part[384 + tid]));
        float sa = __ldg(g_sa + (size_t)(l * NN1 + n1) * PP + blockIdx.x * BM + tid);
        g_maxdot[(size_t)pair * PP + blockIdx.x * BM + tid] = v * sa;
    }
}

// ---------------------------------------------------------------------------
// Kernel 3: sp = sqrt(max(2-2*smax,1e-12))/2 * mask[n1,p]; per-pair max over p
// ---------------------------------------------------------------------------
__global__ __launch_bounds__(256) void sp_kernel(const float* __restrict__ mask) {
    const int pair = blockIdx.x;
    const int n1 = (pair >> 3) & 7;
    const int tid = threadIdx.x;
    __shared__ float red[256];
    float m = -1.0f;
    for (int p = tid; p < PP; p += 256) {
        float s  = g_maxdot[pair * PP + p];
        float d2 = fmaxf(2.0f - 2.0f * s, 1e-12f);
        float sp = sqrtf(d2) * 0.5f * mask[n1 * PP + p];
        g_sp[pair * PP + p] = sp;
        m = fmaxf(m, sp);
    }
    red[tid] = m;
    __syncthreads();
    for (int s = 128; s > 0; s >>= 1) {
        if (tid < s) red[tid] = fmaxf(red[tid], red[tid + s]);
        __syncthreads();
    }
    if (tid == 0) g_maxp[pair] = red[0];
}

// ---------------------------------------------------------------------------
// Kernel 4: spbar[n1,p] = mean over (l,n2) of sp
// ---------------------------------------------------------------------------
__global__ __launch_bounds__(256) void spbar_kernel() {
    int idx = blockIdx.x * 256 + threadIdx.x;
    if (idx >= NN1 * PP) return;
    int n1 = idx >> 10;
    int p  = idx & (PP - 1);
    float s = 0.f;
#pragma unroll
    for (int l = 0; l < LL; l++)
#pragma unroll
        for (int n2 = 0; n2 < NN2; n2++)
            s += g_sp[(((size_t)l * NN1 + n1) * NN2 + n2) * PP + p];
    g_spbar[idx] = s * (1.0f / (LL * NN2));
}

// ---------------------------------------------------------------------------
// Kernel 5: scores[n1] = mean over (l,n2) of maxp -> out[0..7]
// ---------------------------------------------------------------------------
__global__ void scores_kernel(float* __restrict__ out) {
    int n1 = threadIdx.x;
    if (n1 < NN1) {
        float s = 0.f;
#pragma unroll
        for (int l = 0; l < LL; l++)
#pragma unroll
            for (int n2 = 0; n2 < NN2; n2++)
                s += g_maxp[(l * NN1 + n1) * NN2 + n2];
        out[n1] = s * (1.0f / (LL * NN2));
    }
}

// ---------------------------------------------------------------------------
// Kernel 6: bilinear resize 32x32 -> 512x512 (half-pixel centers, edge clamp)
// ---------------------------------------------------------------------------
__global__ __launch_bounds__(256) void resize_kernel(float* __restrict__ out) {
    int idx = blockIdx.x * 256 + threadIdx.x;
    if (idx >= NN1 * IMG * IMG) return;
    int n1  = idx >> 18;
    int rem = idx & (IMG * IMG - 1);
    int y = rem >> 9;
    int x = rem & (IMG - 1);

    float sy = (y + 0.5f) * (1.0f / 16.0f) - 0.5f;
    float sx = (x + 0.5f) * (1.0f / 16.0f) - 0.5f;
    int y0 = (int)floorf(sy);
    int x0 = (int)floorf(sx);
    float wy = sy - (float)y0;
    float wx = sx - (float)x0;
    int y0c = min(max(y0, 0), PH - 1);
    int y1c = min(max(y0 + 1, 0), PH - 1);
    int x0c = min(max(x0, 0), PW - 1);
    int x1c = min(max(x0 + 1, 0), PW - 1);

    const float* sb = g_spbar + n1 * PP;
    float v00 = sb[y0c * PW + x0c];
    float v01 = sb[y0c * PW + x1c];
    float v10 = sb[y1c * PW + x0c];
    float v11 = sb[y1c * PW + x1c];
    float v = (1.f - wy) * ((1.f - wx) * v00 + wx * v01)
            +        wy  * ((1.f - wx) * v10 + wx * v11);
    out[8 + idx] = v;
}

// ---------------------------------------------------------------------------
extern "C" void kernel_launch(void* const* d_in, const int* in_sizes, int n_in,
                              void* d_out, int out_size) {
    const float* feats  = (const float*)d_in[0];
    const float* nfeats = (const float*)d_in[1];
    const float* mask   = (const float*)d_in[2];
    float* out = (float*)d_out;

    const int rows = LL * NN1 * PP;  // 16384 rows per tensor

    normq_kernel<<<rows / 8, 256>>>(feats, 0, rows);
    normq_kernel<<<rows / 8, 256>>>(nfeats, 1, rows);

    dim3 grid(PP / BM, LL * NN1 * NN2);  // (8, 128)
    distmax_i8<<<grid, 256>>>();

    sp_kernel<<<LL * NN1 * NN2, 256>>>(mask);
    spbar_kernel<<<(NN1 * PP + 255) / 256, 256>>>();
    scores_kernel<<<1, 32>>>(out);
    resize_kernel<<<(NN1 * IMG * IMG + 255) / 256, 256>>>(out);
}

// round 7
// speedup vs baseline: 2.4273x; 2.4273x over previous
#include <cuda_runtime.h>
#include <cuda_bf16.h>
#include <math.h>
#include <stdint.h>

#define LL 2
#define NN1 8
#define NN2 8
#define PP 1024
#define DD 768
#define PH 32
#define PW 32
#define IMG 512

// Scratch (device globals; no allocation allowed)
__device__ __nv_bfloat16 g_fa[LL * NN1 * PP * DD];  // normalized feats (bf16)
__device__ __nv_bfloat16 g_fb[LL * NN2 * PP * DD];  // normalized nfeats (bf16)
__device__ float g_maxdot[LL * NN1 * NN2 * PP];     // max_p2 cos-sim
__device__ float g_sp[LL * NN1 * NN2 * PP];
__device__ float g_maxp[LL * NN1 * NN2];
__device__ float g_spbar[NN1 * PP];

// ---------------------------------------------------------------------------
// Kernel 1: L2-normalize rows of [rows, 768] -> bf16. One warp per row.
// ---------------------------------------------------------------------------
__global__ __launch_bounds__(256) void normalize_kernel(const float* __restrict__ in,
                                                        int which, int nrows) {
    int row  = blockIdx.x * 8 + (threadIdx.x >> 5);
    int lane = threadIdx.x & 31;
    if (row >= nrows) return;
    __nv_bfloat16* outbase = which ? g_fb : g_fa;
    const float4* src = (const float4*)(in + (size_t)row * DD);
    __nv_bfloat162* dst = (__nv_bfloat162*)(outbase + (size_t)row * DD);

    float4 v[6];
    float ss = 0.f;
#pragma unroll
    for (int i = 0; i < 6; i++) {
        v[i] = src[lane + 32 * i];
        ss += v[i].x * v[i].x + v[i].y * v[i].y + v[i].z * v[i].z + v[i].w * v[i].w;
    }
#pragma unroll
    for (int o = 16; o > 0; o >>= 1) ss += __shfl_xor_sync(0xffffffffu, ss, o);
    float inv = 1.0f / sqrtf(ss);
#pragma unroll
    for (int i = 0; i < 6; i++) {
        int e = lane + 32 * i;
        dst[e * 2 + 0] = __floats2bfloat162_rn(v[i].x * inv, v[i].y * inv);
        dst[e * 2 + 1] = __floats2bfloat162_rn(v[i].z * inv, v[i].w * inv);
    }
}

// ---------------------------------------------------------------------------
// Kernel 2: fused bf16 mma.sync GEMM + row-max (v2, fixed B fragment map).
// Pair = (l,n1,n2): S = A[1024,768]*B[1024,768]^T; keep row max over columns.
// Block: 128-row strip of A. Flat 96-stage pipeline over (8 col tiles x 12
// K-stages of 64). 256 thr = 8 warps (2m x 4n), warp tile 64x32,
// mma.m16n8k16.bf16, double-buffered cp.async, rows padded to 144B.
// 2 CTAs/SM to fill barrier bubbles.
// ---------------------------------------------------------------------------
#define BM 128
#define BN 128
#define RSB 144               // smem row stride in bytes (128 + 16 pad)
#define ABUF (128 * RSB)      // one buffer of one matrix = 18432 B
#define OFF_B (2 * ABUF)      // 36864
#define OFF_PART (4 * ABUF)   // 73728
#define SMEM_BYTES (OFF_PART + 4 * 128 * 4)  // 75776

#define CP16(dst_u32, src_ptr) \
    asm volatile("cp.async.cg.shared.global [%0], [%1], 16;\n" :: "r"(dst_u32), "l"(src_ptr))

__device__ __forceinline__ void ldsm4(uint32_t* r, uint32_t addr) {
    asm volatile("ldmatrix.sync.aligned.m8n8.x4.shared.b16 {%0,%1,%2,%3}, [%4];"
                 : "=r"(r[0]), "=r"(r[1]), "=r"(r[2]), "=r"(r[3]) : "r"(addr));
}

__global__ __launch_bounds__(256, 2) void distmax_bf16_v2() {
    extern __shared__ char dsm[];
    uint32_t sm = (uint32_t)__cvta_generic_to_shared(dsm);
    float* part = (float*)(dsm + OFF_PART);

    const int pair = blockIdx.y;          // ((l*8 + n1)*8 + n2)
    const int l  = pair >> 6;
    const int n1 = (pair >> 3) & 7;
    const int n2 = pair & 7;
    const __nv_bfloat16* __restrict__ A =
        g_fa + (((size_t)(l * NN1 + n1)) * PP + blockIdx.x * BM) * DD;
    const __nv_bfloat16* __restrict__ B = g_fb + ((size_t)(l * NN2 + n2)) * PP * DD;

    const int tid  = threadIdx.x;
    const int lane = tid & 31;
    const int warp = tid >> 5;
    const int wm = warp >> 2;        // 0..1
    const int wn = warp & 3;         // 0..3
    const int g  = lane >> 2;        // 0..7
    const int t4 = lane & 3;         // 0..3
    const int sub = lane >> 3;       // 0..3 (ldmatrix sub-matrix)
    const int lr8 = lane & 7;

    // cp.async: 4 chunks per matrix per stage; each eighth-warp = one 128B row
    const int rB = tid >> 3;         // 0..31
    const int cc = tid & 7;          // 16B chunk within 128B row
    uint32_t dA[4], dB[4];
    const __nv_bfloat16 *aS[4], *bS[4];
#pragma unroll
    for (int i = 0; i < 4; i++) {
        int r = rB + 32 * i;
        dA[i] = sm + (uint32_t)(r * RSB + cc * 16);
        dB[i] = sm + OFF_B + (uint32_t)(r * RSB + cc * 16);
        aS[i] = A + (size_t)r * DD + cc * 8;
        bS[i] = B + (size_t)r * DD + cc * 8;
    }

    // ldmatrix per-lane byte offsets within a buffer (R4-proven mapping):
    // A: rows from sub&1, k from sub>>1 ; B: rows from sub>>1, k from sub&1
    const uint32_t aLds = (uint32_t)((wm * 64 + (sub & 1) * 8 + lr8) * RSB +
                                     (sub >> 1) * 16);
    const uint32_t bLds = (uint32_t)((wn * 32 + (sub >> 1) * 8 + lr8) * RSB +
                                     (sub & 1) * 16);

    float rmax[4][2];
#pragma unroll
    for (int i = 0; i < 4; i++) { rmax[i][0] = -2.f; rmax[i][1] = -2.f; }

    // stage s = ct*12 + kstep ; issue(s) loads A[.,k*64..] and B rows of tile ct
    int ct_n = 0, k_n = 0;  // (ct,k) of the NEXT stage to issue
    auto issue = [&](int st) {
        uint32_t bo = (uint32_t)((st & 1) * ABUF);
        int ko = k_n * 64;
        size_t bco = (size_t)ct_n * BN * DD + ko;
#pragma unroll
        for (int i = 0; i < 4; i++) CP16(dA[i] + bo, aS[i] + ko);
#pragma unroll
        for (int i = 0; i < 4; i++) CP16(dB[i] + bo, bS[i] + bco);
        asm volatile("cp.async.commit_group;\n");
        if (++k_n == 12) { k_n = 0; ct_n++; }
    };

    issue(0);   // prime (advances counters to stage 1)

    float acc[4][4][4];
    int kc = 0;  // kstep of current stage

    for (int s = 0; s < 96; s++) {
        if (s + 1 < 96) {
            issue(s + 1);
            asm volatile("cp.async.wait_group 1;\n");
        } else {
            asm volatile("cp.async.wait_group 0;\n");
        }
        __syncthreads();

        if (kc == 0) {
#pragma unroll
            for (int mi = 0; mi < 4; mi++)
#pragma unroll
                for (int ni = 0; ni < 4; ni++)
#pragma unroll
                    for (int r = 0; r < 4; r++) acc[mi][ni][r] = 0.f;
        }

        const uint32_t aBuf = sm + (uint32_t)((s & 1) * ABUF);
        const uint32_t bBuf = sm + OFF_B + (uint32_t)((s & 1) * ABUF);

#pragma unroll
        for (int k16 = 0; k16 < 4; k16++) {
            uint32_t a[4][4], b[2][4];
#pragma unroll
            for (int mi = 0; mi < 4; mi++)
                ldsm4(a[mi], aBuf + aLds + (uint32_t)(mi * 16 * RSB + k16 * 32));
#pragma unroll
            for (int np = 0; np < 2; np++)
                ldsm4(b[np], bBuf + bLds + (uint32_t)(np * 16 * RSB + k16 * 32));
#pragma unroll
            for (int mi = 0; mi < 4; mi++)
#pragma unroll
                for (int ni = 0; ni < 4; ni++) {
                    asm volatile(
                        "mma.sync.aligned.m16n8k16.row.col.f32.bf16.bf16.f32 "
                        "{%0,%1,%2,%3},{%4,%5,%6,%7},{%8,%9},{%0,%1,%2,%3};\n"
                        : "+f"(acc[mi][ni][0]), "+f"(acc[mi][ni][1]),
                          "+f"(acc[mi][ni][2]), "+f"(acc[mi][ni][3])
                        : "r"(a[mi][0]), "r"(a[mi][1]), "r"(a[mi][2]), "r"(a[mi][3]),
                          "r"(b[ni >> 1][(ni & 1) * 2]), "r"(b[ni >> 1][(ni & 1) * 2 + 1]));
                }
        }
        __syncthreads();

        if (kc == 11) {
            // column tile finished: fold into running row max
            // c0,c1 -> row g; c2,c3 -> row g+8
#pragma unroll
            for (int mi = 0; mi < 4; mi++) {
                float m0 = -2.f, m1 = -2.f;
#pragma unroll
                for (int ni = 0; ni < 4; ni++) {
                    m0 = fmaxf(m0, fmaxf(acc[mi][ni][0], acc[mi][ni][1]));
                    m1 = fmaxf(m1, fmaxf(acc[mi][ni][2], acc[mi][ni][3]));
                }
                rmax[mi][0] = fmaxf(rmax[mi][0], m0);
                rmax[mi][1] = fmaxf(rmax[mi][1], m1);
            }
            kc = 0;
        } else {
            kc++;
        }
    }

    // reduce across the 4 lanes sharing g (t4 = lane&3)
#pragma unroll
    for (int o = 1; o <= 2; o <<= 1) {
#pragma unroll
        for (int mi = 0; mi < 4; mi++) {
            rmax[mi][0] = fmaxf(rmax[mi][0], __shfl_xor_sync(0xffffffffu, rmax[mi][0], o));
            rmax[mi][1] = fmaxf(rmax[mi][1], __shfl_xor_sync(0xffffffffu, rmax[mi][1], o));
        }
    }
    if (t4 == 0) {
#pragma unroll
        for (int mi = 0; mi < 4; mi++) {
            int r = wm * 64 + mi * 16 + g;
            part[wn * 128 + r] = rmax[mi][0];
            part[wn * 128 + r + 8] = rmax[mi][1];
        }
    }
    __syncthreads();
    if (tid < 128) {
        float v = fmaxf(fmaxf(part[tid], part[128 + tid]),
                        fmaxf(part[256 + tid], part[384 + tid]));
        g_maxdot[(size_t)pair * PP + blockIdx.x * BM + tid] = v;
    }
}

// ---------------------------------------------------------------------------
// Kernel 3: sp = sqrt(max(2-2*smax,1e-12))/2 * mask[n1,p]; per-pair max over p
// ---------------------------------------------------------------------------
__global__ __launch_bounds__(256) void sp_kernel(const float* __restrict__ mask) {
    const int pair = blockIdx.x;
    const int n1 = (pair >> 3) & 7;
    const int tid = threadIdx.x;
    __shared__ float red[256];
    float m = -1.0f;
    for (int p = tid; p < PP; p += 256) {
        float s  = g_maxdot[pair * PP + p];
        float d2 = fmaxf(2.0f - 2.0f * s, 1e-12f);
        float sp = sqrtf(d2) * 0.5f * mask[n1 * PP + p];
        g_sp[pair * PP + p] = sp;
        m = fmaxf(m, sp);
    }
    red[tid] = m;
    __syncthreads();
    for (int s = 128; s > 0; s >>= 1) {
        if (tid < s) red[tid] = fmaxf(red[tid], red[tid + s]);
        __syncthreads();
    }
    if (tid == 0) g_maxp[pair] = red[0];
}

// ---------------------------------------------------------------------------
// Kernel 4: spbar[n1,p] = mean over (l,n2) of sp
// ---------------------------------------------------------------------------
__global__ __launch_bounds__(256) void spbar_kernel() {
    int idx = blockIdx.x * 256 + threadIdx.x;
    if (idx >= NN1 * PP) return;
    int n1 = idx >> 10;
    int p  = idx & (PP - 1);
    float s = 0.f;
#pragma unroll
    for (int l = 0; l < LL; l++)
#pragma unroll
        for (int n2 = 0; n2 < NN2; n2++)
            s += g_sp[(((size_t)l * NN1 + n1) * NN2 + n2) * PP + p];
    g_spbar[idx] = s * (1.0f / (LL * NN2));
}

// ---------------------------------------------------------------------------
// Kernel 5: scores[n1] = mean over (l,n2) of maxp -> out[0..7]
// ---------------------------------------------------------------------------
__global__ void scores_kernel(float* __restrict__ out) {
    int n1 = threadIdx.x;
    if (n1 < NN1) {
        float s = 0.f;
#pragma unroll
        for (int l = 0; l < LL; l++)
#pragma unroll
            for (int n2 = 0; n2 < NN2; n2++)
                s += g_maxp[(l * NN1 + n1) * NN2 + n2];
        out[n1] = s * (1.0f / (LL * NN2));
    }
}

// ---------------------------------------------------------------------------
// Kernel 6: bilinear resize 32x32 -> 512x512 (half-pixel centers, edge clamp)
// ---------------------------------------------------------------------------
__global__ __launch_bounds__(256) void resize_kernel(float* __restrict__ out) {
    int idx = blockIdx.x * 256 + threadIdx.x;
    if (idx >= NN1 * IMG * IMG) return;
    int n1  = idx >> 18;
    int rem = idx & (IMG * IMG - 1);
    int y = rem >> 9;
    int x = rem & (IMG - 1);

    float sy = (y + 0.5f) * (1.0f / 16.0f) - 0.5f;
    float sx = (x + 0.5f) * (1.0f / 16.0f) - 0.5f;
    int y0 = (int)floorf(sy);
    int x0 = (int)floorf(sx);
    float wy = sy - (float)y0;
    float wx = sx - (float)x0;
    int y0c = min(max(y0, 0), PH - 1);
    int y1c = min(max(y0 + 1, 0), PH - 1);
    int x0c = min(max(x0, 0), PW - 1);
    int x1c = min(max(x0 + 1, 0), PW - 1);

    const float* sb = g_spbar + n1 * PP;
    float v00 = sb[y0c * PW + x0c];
    float v01 = sb[y0c * PW + x1c];
    float v10 = sb[y1c * PW + x0c];
    float v11 = sb[y1c * PW + x1c];
    float v = (1.f - wy) * ((1.f - wx) * v00 + wx * v01)
            +        wy  * ((1.f - wx) * v10 + wx * v11);
    out[8 + idx] = v;
}

// ---------------------------------------------------------------------------
extern "C" void kernel_launch(void* const* d_in, const int* in_sizes, int n_in,
                              void* d_out, int out_size) {
    const float* feats  = (const float*)d_in[0];
    const float* nfeats = (const float*)d_in[1];
    const float* mask   = (const float*)d_in[2];
    float* out = (float*)d_out;

    const int rows = LL * NN1 * PP;  // 16384 rows per tensor

    normalize_kernel<<<rows / 8, 256>>>(feats, 0, rows);
    normalize_kernel<<<rows / 8, 256>>>(nfeats, 1, rows);

    cudaFuncSetAttribute(distmax_bf16_v2,
                         cudaFuncAttributeMaxDynamicSharedMemorySize, SMEM_BYTES);
    dim3 grid(PP / BM, LL * NN1 * NN2);  // (8, 128)
    distmax_bf16_v2<<<grid, 256, SMEM_BYTES>>>();

    sp_kernel<<<LL * NN1 * NN2, 256>>>(mask);
    spbar_kernel<<<(NN1 * PP + 255) / 256, 256>>>();
    scores_kernel<<<1, 32>>>(out);
    resize_kernel<<<(NN1 * IMG * IMG + 255) / 256, 256>>>(out);
}